// round 5
// baseline (speedup 1.0000x reference)
#include <cuda_runtime.h>

#define BATCH  32
#define NP     4096
#define NSLOT  (2 * BATCH)            // one grid per (cloud w, batch b)
#define GD     48
#define NCELLS (GD * GD * GD)         // 110592
#define GMIN   (-7.5f)
#define H      (0.3125f)              // 15 / 48
#define INVH   (3.2f)

// Static scratch (allocation-free).
__device__ int       g_cnt[NSLOT][NCELLS];   // per-cell point counts
__device__ unsigned  g_cs [NSLOT][NCELLS];   // packed (start<<16)|count
__device__ int       g_cur[NSLOT][NCELLS];   // scatter cursors (= start)
__device__ float4    g_pts[NSLOT][NP];       // binned points: (-2x,-2y,-2z,||c||^2)
__device__ unsigned short g_qid[NSLOT][NP];  // original index of binned point
__device__ float     g_dist[NSLOT][NP];      // per-query min dist, by ORIGINAL index

static __device__ __forceinline__ int cell_coord(float v) {
    int c = (int)floorf((v - GMIN) * INVH);
    return min(max(c, 0), GD - 1);
}

// ---------------------------------------------------------------------------
// 1) zero the count arrays (vectorized)
// ---------------------------------------------------------------------------
__global__ void zero_kernel() {
    int4* p = (int4*)g_cnt;
    int n = NSLOT * NCELLS / 4;
    int i = blockIdx.x * blockDim.x + threadIdx.x;
    if (i < n) p[i] = make_int4(0, 0, 0, 0);
}

// ---------------------------------------------------------------------------
// 2) histogram points into cells
// ---------------------------------------------------------------------------
__global__ void count_kernel(const float* __restrict__ x1,
                             const float* __restrict__ x2) {
    int gid = blockIdx.x * blockDim.x + threadIdx.x;   // 0 .. NSLOT*NP-1
    if (gid >= NSLOT * NP) return;
    int s = gid / NP;                 // slot = w*BATCH + b
    int p = gid - s * NP;
    int w = s / BATCH;
    int b = s - w * BATCH;
    const float* src = (w ? x2 : x1) + ((size_t)b * NP + p) * 3;
    int cx = cell_coord(src[0]);
    int cy = cell_coord(src[1]);
    int cz = cell_coord(src[2]);
    atomicAdd(&g_cnt[s][(cz * GD + cy) * GD + cx], 1);
}

// ---------------------------------------------------------------------------
// 3) per-slot exclusive scan of counts -> packed (start,count) + cursors.
//    One block (1024 threads) per slot; NCELLS = 1024 * 108 exactly.
// ---------------------------------------------------------------------------
__global__ void __launch_bounds__(1024)
scan_kernel() {
    const int s = blockIdx.x;
    const int tid = threadIdx.x;
    const int per = NCELLS / 1024;    // 108
    const int base = tid * per;

    int lsum = 0;
    #pragma unroll 4
    for (int i = 0; i < per; i++) lsum += g_cnt[s][base + i];

    // block scan of 1024 partials
    __shared__ int wsum[32];
    int lane = tid & 31, wid = tid >> 5;
    int v = lsum;
    #pragma unroll
    for (int o = 1; o < 32; o <<= 1) {
        int n = __shfl_up_sync(0xffffffffu, v, o);
        if (lane >= o) v += n;
    }
    if (lane == 31) wsum[wid] = v;
    __syncthreads();
    if (wid == 0) {
        int t = wsum[lane];
        #pragma unroll
        for (int o = 1; o < 32; o <<= 1) {
            int n = __shfl_up_sync(0xffffffffu, t, o);
            if (lane >= o) t += n;
        }
        wsum[lane] = t;
    }
    __syncthreads();
    int offset = (v - lsum) + (wid > 0 ? wsum[wid - 1] : 0);  // exclusive prefix

    int run = offset;
    for (int i = 0; i < per; i++) {
        int c = g_cnt[s][base + i];
        g_cs[s][base + i] = ((unsigned)run << 16) | (unsigned)c;
        g_cur[s][base + i] = run;
        run += c;
    }
}

// ---------------------------------------------------------------------------
// 4) scatter points into binned order, preprocessed as (-2x,-2y,-2z,||c||^2)
// ---------------------------------------------------------------------------
__global__ void scatter_kernel(const float* __restrict__ x1,
                               const float* __restrict__ x2) {
    int gid = blockIdx.x * blockDim.x + threadIdx.x;
    if (gid >= NSLOT * NP) return;
    int s = gid / NP;
    int p = gid - s * NP;
    int w = s / BATCH;
    int b = s - w * BATCH;
    const float* src = (w ? x2 : x1) + ((size_t)b * NP + p) * 3;
    float x = src[0], y = src[1], z = src[2];
    int cx = cell_coord(x), cy = cell_coord(y), cz = cell_coord(z);
    int pos = atomicAdd(&g_cur[s][(cz * GD + cy) * GD + cx], 1);
    g_pts[s][pos] = make_float4(-2.0f * x, -2.0f * y, -2.0f * z,
                                x * x + y * y + z * z);
    g_qid[s][pos] = (unsigned short)p;
}

// ---------------------------------------------------------------------------
// 5) query: expanding-ring nearest-neighbor search.
//    Queries iterate their OWN binned order (warp-coherent cells).
// ---------------------------------------------------------------------------
__global__ void __launch_bounds__(256)
query_kernel() {
    const int dir = blockIdx.z;
    const int b   = blockIdx.y;
    const int sq  = dir * BATCH + b;          // query slot
    const int sc  = (dir ^ 1) * BATCH + b;    // candidate slot
    const int j   = blockIdx.x * 256 + threadIdx.x;

    float4 qp = g_pts[sq][j];
    int qid = g_qid[sq][j];
    float qx = -0.5f * qp.x, qy = -0.5f * qp.y, qz = -0.5f * qp.z;
    float qq = qp.w;

    int cx = cell_coord(qx), cy = cell_coord(qy), cz = cell_coord(qz);

    const unsigned* __restrict__ cs  = g_cs[sc];
    const float4*   __restrict__ pts = g_pts[sc];

    float m = __int_as_float(0x7f800000);     // min of (cc - 2 q.c)

    for (int r = 0;; r++) {
        int zlo = max(cz - r, 0), zhi = min(cz + r, GD - 1);
        int ylo = max(cy - r, 0), yhi = min(cy + r, GD - 1);
        int xlo = max(cx - r, 0), xhi = min(cx + r, GD - 1);
        for (int z = zlo; z <= zhi; z++) {
            bool ze = (z == cz - r) || (z == cz + r);
            for (int y = ylo; y <= yhi; y++) {
                bool edge = ze || (y == cy - r) || (y == cy + r);
                int rowbase = (z * GD + y) * GD;
                if (edge) {
                    for (int x = xlo; x <= xhi; x++) {
                        unsigned e = cs[rowbase + x];
                        int cnt = e & 0xffff, st = e >> 16;
                        for (int k = 0; k < cnt; k++) {
                            float4 c = pts[st + k];
                            float v = fmaf(qx, c.x,
                                      fmaf(qy, c.y,
                                      fmaf(qz, c.z, c.w)));
                            m = fminf(m, v);
                        }
                    }
                } else {
                    if (cx - r >= 0) {
                        unsigned e = cs[rowbase + cx - r];
                        int cnt = e & 0xffff, st = e >> 16;
                        for (int k = 0; k < cnt; k++) {
                            float4 c = pts[st + k];
                            float v = fmaf(qx, c.x,
                                      fmaf(qy, c.y,
                                      fmaf(qz, c.z, c.w)));
                            m = fminf(m, v);
                        }
                    }
                    if (cx + r < GD) {
                        unsigned e = cs[rowbase + cx + r];
                        int cnt = e & 0xffff, st = e >> 16;
                        for (int k = 0; k < cnt; k++) {
                            float4 c = pts[st + k];
                            float v = fmaf(qx, c.x,
                                      fmaf(qy, c.y,
                                      fmaf(qz, c.z, c.w)));
                            m = fminf(m, v);
                        }
                    }
                }
            }
        }
        float bd = qq + m;                    // best actual distance^2 so far
        float rh = (float)r * H;
        // conservative stop: unseen points are >= r*H away
        if (bd * 1.0001f <= rh * rh || r >= GD) break;
    }

    g_dist[sq][qid] = qq + m;
}

// ---------------------------------------------------------------------------
// 6) deterministic fixed-order reduce: out[b] = (sum_d0 + sum_d1) / NP
// ---------------------------------------------------------------------------
__global__ void __launch_bounds__(256)
reduce_kernel(float* __restrict__ out) {
    const int b = blockIdx.x;
    const int tid = threadIdx.x;
    float s = 0.0f;
    #pragma unroll
    for (int d = 0; d < 2; d++)
        for (int i = tid; i < NP; i += 256)
            s += g_dist[d * BATCH + b][i];

    __shared__ float red[256];
    red[tid] = s;
    __syncthreads();
    #pragma unroll
    for (int o = 128; o > 0; o >>= 1) {
        if (tid < o) red[tid] += red[tid + o];
        __syncthreads();
    }
    if (tid == 0) out[b] = red[0] * (1.0f / (float)NP);
}

extern "C" void kernel_launch(void* const* d_in, const int* in_sizes, int n_in,
                              void* d_out, int out_size) {
    const float* x1 = (const float*)d_in[0];
    const float* x2 = (const float*)d_in[1];
    float* out = (float*)d_out;

    int zn = NSLOT * NCELLS / 4;
    zero_kernel<<<(zn + 255) / 256, 256>>>();
    int pn = NSLOT * NP;
    count_kernel<<<(pn + 255) / 256, 256>>>(x1, x2);
    scan_kernel<<<NSLOT, 1024>>>();
    scatter_kernel<<<(pn + 255) / 256, 256>>>(x1, x2);
    query_kernel<<<dim3(NP / 256, BATCH, 2), 256>>>();
    reduce_kernel<<<BATCH, 256>>>(out);
}

// round 6
// speedup vs baseline: 2.4343x; 2.4343x over previous
#include <cuda_runtime.h>

#define BATCH  32
#define NP     4096
#define NSLOT  (2 * BATCH)
#define GD     40
#define NCELLS (GD * GD * GD)         // 64000
#define GMIN   (-7.5f)
#define H      (0.375f)
#define INVH   (2.6666666667f)

__device__ int            g_cnt[NSLOT][NCELLS];
__device__ unsigned       g_cs [NSLOT][NCELLS];   // (start<<16)|count
__device__ int            g_cur[NSLOT][NCELLS];
__device__ float4         g_pts[NSLOT][NP];       // (-2x,-2y,-2z,||c||^2), binned
__device__ unsigned short g_qid[NSLOT][NP];
__device__ float          g_dist[NSLOT][NP];      // by ORIGINAL index

static __device__ __forceinline__ int cell_coord(float v) {
    int c = (int)floorf((v - GMIN) * INVH);
    return min(max(c, 0), GD - 1);
}

// 1) zero counts
__global__ void zero_kernel() {
    int4* p = (int4*)g_cnt;
    int n = NSLOT * NCELLS / 4;
    int i = blockIdx.x * blockDim.x + threadIdx.x;
    if (i < n) p[i] = make_int4(0, 0, 0, 0);
}

// 2) histogram
__global__ void count_kernel(const float* __restrict__ x1,
                             const float* __restrict__ x2) {
    int gid = blockIdx.x * blockDim.x + threadIdx.x;
    if (gid >= NSLOT * NP) return;
    int s = gid / NP, p = gid - s * NP;
    int w = s / BATCH, b = s - w * BATCH;
    const float* src = (w ? x2 : x1) + ((size_t)b * NP + p) * 3;
    int cx = cell_coord(src[0]), cy = cell_coord(src[1]), cz = cell_coord(src[2]);
    atomicAdd(&g_cnt[s][(cz * GD + cy) * GD + cx], 1);
}

// 3) per-slot exclusive scan (512 threads, 125 cells each; 512*125 = 64000)
__global__ void __launch_bounds__(512)
scan_kernel() {
    const int s = blockIdx.x, tid = threadIdx.x;
    const int per = NCELLS / 512;     // 125
    const int base = tid * per;

    int lsum = 0;
    for (int i = 0; i < per; i++) lsum += g_cnt[s][base + i];

    __shared__ int wsum[16];
    int lane = tid & 31, wid = tid >> 5;
    int v = lsum;
    #pragma unroll
    for (int o = 1; o < 32; o <<= 1) {
        int n = __shfl_up_sync(0xffffffffu, v, o);
        if (lane >= o) v += n;
    }
    if (lane == 31) wsum[wid] = v;
    __syncthreads();
    if (wid == 0) {
        int t = (lane < 16) ? wsum[lane] : 0;
        #pragma unroll
        for (int o = 1; o < 16; o <<= 1) {
            int n = __shfl_up_sync(0xffffffffu, t, o);
            if (lane >= o) t += n;
        }
        if (lane < 16) wsum[lane] = t;
    }
    __syncthreads();
    int offset = (v - lsum) + (wid > 0 ? wsum[wid - 1] : 0);

    int run = offset;
    for (int i = 0; i < per; i++) {
        int c = g_cnt[s][base + i];
        g_cs[s][base + i] = ((unsigned)run << 16) | (unsigned)c;
        g_cur[s][base + i] = run;
        run += c;
    }
}

// 4) scatter into binned order
__global__ void scatter_kernel(const float* __restrict__ x1,
                               const float* __restrict__ x2) {
    int gid = blockIdx.x * blockDim.x + threadIdx.x;
    if (gid >= NSLOT * NP) return;
    int s = gid / NP, p = gid - s * NP;
    int w = s / BATCH, b = s - w * BATCH;
    const float* src = (w ? x2 : x1) + ((size_t)b * NP + p) * 3;
    float x = src[0], y = src[1], z = src[2];
    int cx = cell_coord(x), cy = cell_coord(y), cz = cell_coord(z);
    int pos = atomicAdd(&g_cur[s][(cz * GD + cy) * GD + cx], 1);
    g_pts[s][pos] = make_float4(-2.0f * x, -2.0f * y, -2.0f * z,
                                x * x + y * y + z * z);
    g_qid[s][pos] = (unsigned short)p;
}

// 5) warp-cooperative query: one query per warp, box scan via contiguous
//    row-ranges; expand box until exact face-distance bound proves the min.
__global__ void __launch_bounds__(256)
query_kernel() {
    const unsigned FULL = 0xffffffffu;
    const int dir = blockIdx.z;
    const int b   = blockIdx.y;
    const int sq  = dir * BATCH + b;
    const int sc  = (dir ^ 1) * BATCH + b;
    const int wq  = blockIdx.x * 8 + (threadIdx.x >> 5);   // query (binned order)
    const int lane = threadIdx.x & 31;

    float4 qp = g_pts[sq][wq];
    int qid = g_qid[sq][wq];
    // exact reconstruction: -0.5f * (-2.0f*x) == x bitwise
    float qx = -0.5f * qp.x, qy = -0.5f * qp.y, qz = -0.5f * qp.z;
    float qq = qp.w;

    const int cx = cell_coord(qx), cy = cell_coord(qy), cz = cell_coord(qz);

    const unsigned* __restrict__ cs  = g_cs[sc];
    const float4*   __restrict__ pts = g_pts[sc];

    const float INF = __int_as_float(0x7f800000);
    float m = INF;                    // min of (cc - 2 q.c)

    for (int r = 1; r <= GD; r++) {
        const int zlo = max(cz - r, 0), zhi = min(cz + r, GD - 1);
        const int ylo = max(cy - r, 0), yhi = min(cy + r, GD - 1);
        const int xlo = max(cx - r, 0), xhi = min(cx + r, GD - 1);
        const int ny = yhi - ylo + 1;
        const int nrows = (zhi - zlo + 1) * ny;

        for (int rb = 0; rb < nrows; rb += 32) {
            int rs = 0, re = 0;
            int ri = rb + lane;
            if (ri < nrows) {
                int z = zlo + ri / ny;
                int y = ylo + ri - (ri / ny) * ny;
                int rowbase = (z * GD + y) * GD;
                unsigned e0 = cs[rowbase + xlo];
                unsigned e1 = cs[rowbase + xhi];
                rs = (int)(e0 >> 16);
                re = (int)((e1 >> 16) + (e1 & 0xffffu));
            }
            int nbatch = min(nrows - rb, 32);
            for (int rr = 0; rr < nbatch; rr++) {
                int s0 = __shfl_sync(FULL, rs, rr);
                int e0 = __shfl_sync(FULL, re, rr);
                for (int idx = s0 + lane; idx < e0; idx += 32) {
                    float4 c = pts[idx];
                    m = fminf(m, fmaf(qx, c.x,
                                 fmaf(qy, c.y,
                                 fmaf(qz, c.z, c.w))));
                }
            }
        }

        // warp-reduce the min
        float mm = m;
        #pragma unroll
        for (int o = 16; o > 0; o >>= 1)
            mm = fminf(mm, __shfl_xor_sync(FULL, mm, o));

        // exact bound: distance from q to nearest uncovered box face
        // (faces at the grid edge are fully covered -> +inf)
        float bnd = INF;
        if (cx - r > 0)      bnd = fminf(bnd, qx - (GMIN + (float)(cx - r) * H));
        if (cx + r < GD - 1) bnd = fminf(bnd, (GMIN + (float)(cx + r + 1) * H) - qx);
        if (cy - r > 0)      bnd = fminf(bnd, qy - (GMIN + (float)(cy - r) * H));
        if (cy + r < GD - 1) bnd = fminf(bnd, (GMIN + (float)(cy + r + 1) * H) - qy);
        if (cz - r > 0)      bnd = fminf(bnd, qz - (GMIN + (float)(cz - r) * H));
        if (cz + r < GD - 1) bnd = fminf(bnd, (GMIN + (float)(cz + r + 1) * H) - qz);

        float bd = qq + mm;
        if (bd <= bnd * bnd || r == GD) {
            if (lane == 0) g_dist[sq][qid] = bd;
            break;
        }
        m = mm;   // carry best across expansions (box r+1 is a superset)
    }
}

// 6) deterministic fixed-order reduce
__global__ void __launch_bounds__(256)
reduce_kernel(float* __restrict__ out) {
    const int b = blockIdx.x, tid = threadIdx.x;
    float s = 0.0f;
    #pragma unroll
    for (int d = 0; d < 2; d++)
        for (int i = tid; i < NP; i += 256)
            s += g_dist[d * BATCH + b][i];

    __shared__ float red[256];
    red[tid] = s;
    __syncthreads();
    #pragma unroll
    for (int o = 128; o > 0; o >>= 1) {
        if (tid < o) red[tid] += red[tid + o];
        __syncthreads();
    }
    if (tid == 0) out[b] = red[0] * (1.0f / (float)NP);
}

extern "C" void kernel_launch(void* const* d_in, const int* in_sizes, int n_in,
                              void* d_out, int out_size) {
    const float* x1 = (const float*)d_in[0];
    const float* x2 = (const float*)d_in[1];
    float* out = (float*)d_out;

    int zn = NSLOT * NCELLS / 4;
    zero_kernel<<<(zn + 255) / 256, 256>>>();
    int pn = NSLOT * NP;
    count_kernel<<<(pn + 255) / 256, 256>>>(x1, x2);
    scan_kernel<<<NSLOT, 512>>>();
    scatter_kernel<<<(pn + 255) / 256, 256>>>(x1, x2);
    query_kernel<<<dim3(NP / 8, BATCH, 2), 256>>>();
    reduce_kernel<<<BATCH, 256>>>(out);
}